// round 15
// baseline (speedup 1.0000x reference)
#include <cuda_runtime.h>
#include <cstdint>

#define NN 1024
#define HH 512
#define TI 32            // output rows per CTA
#define NWARPS 8
#define NTHREADS (NWARPS*32)
#define RS 14            // ring slots (raw rows); 14*4KB = 56KB -> 4 CTAs/SM
#define ROWB (NN*4)      // bytes per raw row

__device__ __forceinline__ int reflC(int c) {
    if (c < 0) c = -c;
    if (c > HH - 1) c = 2 * (HH - 1) - c;
    return c;
}

__device__ __forceinline__ void tma_row(uint32_t dst, const float* src, uint32_t mbar) {
    asm volatile(
        "cp.async.bulk.shared::cta.global.mbarrier::complete_tx::bytes [%0], [%1], %2, [%3];"
        :: "r"(dst), "l"(src), "r"((uint32_t)ROWB), "r"(mbar) : "memory");
}
__device__ __forceinline__ void mbar_init(uint32_t mbar, uint32_t cnt) {
    asm volatile("mbarrier.init.shared.b64 [%0], %1;" :: "r"(mbar), "r"(cnt) : "memory");
}
__device__ __forceinline__ void mbar_expect(uint32_t mbar, uint32_t bytes) {
    asm volatile("mbarrier.arrive.expect_tx.shared.b64 _, [%0], %1;"
                 :: "r"(mbar), "r"(bytes) : "memory");
}
__device__ __forceinline__ void mbar_arrive(uint32_t mbar) {
    asm volatile("mbarrier.arrive.shared.b64 _, [%0];" :: "r"(mbar) : "memory");
}
__device__ __forceinline__ void mbar_wait(uint32_t mbar, uint32_t parity) {
    asm volatile(
        "{\n\t.reg .pred P;\n\t"
        "W_%=:\n\t"
        "mbarrier.try_wait.parity.acquire.cta.shared::cta.b64 P, [%0], %1, 0x989680;\n\t"
        "@!P bra W_%=;\n\t"
        "}" :: "r"(mbar), "r"(parity) : "memory");
}
__device__ __forceinline__ void stcs2(float* p, float a, float b) {
    asm volatile("st.global.cs.v2.f32 [%0], {%1,%2};" :: "l"(p), "f"(a), "f"(b) : "memory");
}

struct V4 { float s0, s1, d0, d1; };

__device__ __forceinline__ V4 rowlift(const float* rp,
                                      int loff, int offA, int offC,
                                      bool lEdge, bool rEdge) {
    const float4 B = *reinterpret_cast<const float4*>(rp + loff);
    const float4 A = *reinterpret_cast<const float4*>(rp + offA);
    const float4 C = *reinterpret_cast<const float4*>(rp + offC);
    float dm1 = A.w - 0.5f * (A.x + B.x);
    float d0  = B.y - 0.5f * (A.z + B.z);
    float d1  = B.w - 0.5f * (B.x + C.x);
    float d2  = C.y - 0.5f * (B.z + C.z);
    if (lEdge) { dm1 = d1; d0 = B.y - B.z; }
    if (rEdge) { d1 = B.w - B.x; d2 = d0; }
    V4 r;
    r.s0 = B.x + 0.25f * (dm1 + d1);
    r.s1 = B.z + 0.25f * (d0 + d2);
    r.d0 = d0; r.d1 = d1;
    return r;
}

__global__ __launch_bounds__(NTHREADS, 4)
void ilwt2d_occ4_kernel(const float* __restrict__ x, float* __restrict__ out) {
    extern __shared__ __align__(16) float ring[];   // RS * NN floats = 56KB
    __shared__ __align__(8) uint64_t mbars[15];     // [0..6] full, [7] prologue, [8..14] empty

    const int tid  = threadIdx.x;
    const int lane = tid & 31;
    const int w    = tid >> 5;
    const int C0   = w * 64;
    const int i0   = blockIdx.x * TI;
    const int img  = blockIdx.y;
    const float* __restrict__ xp = x + (size_t)img * NN * NN;
    const int rbase = 2 * i0 - 4;

    const uint32_t sring = (uint32_t)__cvta_generic_to_shared(ring);
    const uint32_t mb0   = (uint32_t)__cvta_generic_to_shared(&mbars[0]);
    #define FULLB(g)  (mb0 + (uint32_t)((g) * 8))
    #define PROB()    (mb0 + 56u)
    #define EMPTYB(g) (mb0 + 64u + (uint32_t)((g) * 8))

    if (tid == 0) {
        #pragma unroll
        for (int j = 0; j < 7; ++j) mbar_init(FULLB(j), 1);
        mbar_init(PROB(), 1);
        #pragma unroll
        for (int j = 0; j < 7; ++j) mbar_init(EMPTYB(j), NWARPS);
    }
    __syncthreads();

    // ---- prologue staging: offsets 0..12 (13 rows), slots 0..12 ----
    if (tid == 0) {
        mbar_expect(PROB(), 13u * (uint32_t)ROWB);
        #pragma unroll
        for (int k = 0; k < 13; ++k) {
            int row = max(0, min(NN - 1, rbase + k));
            tma_row(sring + (uint32_t)(k * ROWB), xp + (size_t)row * NN, PROB());
        }
    }

    const int loff = 2 * C0 + 4 * lane;
    const bool lEdge = (loff == 0);
    const bool rEdge = (loff == NN - 4);
    const int offA = lEdge ? loff : loff - 4;
    const int offC = rEdge ? loff : loff + 4;

    #define LSLOT(s) rowlift(ring + (s) * NN, loff, offA, offC, lEdge, rEdge)
    #define LGEN(row_) rowlift(ring + (((row_) - rbase) % RS) * NN, \
                               loff, offA, offC, lEdge, rEdge)

    mbar_wait(PROB(), 0);           // prologue rows 0..12 visible

    // ---- prologue pipeline state (reads offsets 0..8 -> slot == offset) ----
    V4 Ecur  = LSLOT(4);                           // row 2*i0
    const int sm  = 2 * reflC(i0 - 1) - rbase;     // 2 (interior) / 6 (top)
    const int sm2 = 2 * reflC(i0 - 2) - rbase;     // 0 / 8
    V4 Em    = LSLOT(sm);
    V4 Em2   = LSLOT(sm2);
    V4 Om1   = LSLOT(sm + 1);
    V4 Dprev;
    Dprev.s0 = Om1.s0 - 0.5f * (Em2.s0 + Ecur.s0);
    Dprev.s1 = Om1.s1 - 0.5f * (Em2.s1 + Ecur.s1);
    Dprev.d0 = Om1.d0 - 0.5f * (Em2.d0 + Ecur.d0);
    Dprev.d1 = Om1.d1 - 0.5f * (Em2.d1 + Ecur.d1);
    V4 Enext = LSLOT(6);                           // row 2*(i0+1), always interior
    V4 O0    = LSLOT(5);                           // row 2*i0+1
    V4 Dcur;
    Dcur.s0 = O0.s0 - 0.5f * (Em.s0 + Enext.s0);
    Dcur.s1 = O0.s1 - 0.5f * (Em.s1 + Enext.s1);
    Dcur.d0 = O0.d0 - 0.5f * (Em.d0 + Enext.d0);
    Dcur.d1 = O0.d1 - 0.5f * (Em.d1 + Enext.d1);
    __syncthreads();   // all prologue ring reads complete before any main staging

    const int b = img / 3, ch = img - 3 * b;
    const size_t plane = (size_t)HH * HH;
    float* op = out + (size_t)b * 12 * plane + (size_t)ch * plane
                    + (size_t)i0 * HH + C0 + 2 * lane;

    #define CORE(En2, Oi1)                                                      \
        V4 Dnext;                                                               \
        Dnext.s0 = Oi1.s0 - 0.5f * (Ecur.s0 + En2.s0);                          \
        Dnext.s1 = Oi1.s1 - 0.5f * (Ecur.s1 + En2.s1);                          \
        Dnext.d0 = Oi1.d0 - 0.5f * (Ecur.d0 + En2.d0);                          \
        Dnext.d1 = Oi1.d1 - 0.5f * (Ecur.d1 + En2.d1);                          \
        float2 ll = { Ecur.s0 + 0.25f * (Dprev.s0 + Dnext.s0),                  \
                      Ecur.s1 + 0.25f * (Dprev.s1 + Dnext.s1) };                \
        float2 hl = { Ecur.d0 + 0.25f * (Dprev.d0 + Dnext.d0),                  \
                      Ecur.d1 + 0.25f * (Dprev.d1 + Dnext.d1) };                \
        stcs2(op,             ll.x, ll.y);                                      \
        stcs2(op + 3 * plane, Dcur.s0, Dcur.s1);                                \
        stcs2(op + 6 * plane, hl.x, hl.y);                                      \
        stcs2(op + 9 * plane, Dcur.d0, Dcur.d1);                                \
        op += HH;                                                               \
        Ecur = Enext; Enext = En2;                                              \
        Dprev = Dcur; Dcur = Dnext;

    // stage pair (2t+13, 2t+14) into group g at constant slots
    #define STG(t_, g_, s1_, s2_) do {                                          \
        mbar_expect(FULLB(g_), 2u * (uint32_t)ROWB);                            \
        int r1 = min(NN - 1, rbase + 2 * (t_) + 13);                            \
        int r2 = min(NN - 1, rbase + 2 * (t_) + 14);                            \
        tma_row(sring + (uint32_t)((s1_) * ROWB), xp + (size_t)r1 * NN, FULLB(g_)); \
        tma_row(sring + (uint32_t)((s2_) * ROWB), xp + (size_t)r2 * NN, FULLB(g_)); \
    } while (0)

    // ---- phase 1: t = 0..2 — consume prologue slots (no full wait), stage groups 0..2 ----
    #pragma unroll
    for (int t = 0; t < 3; ++t) {
        if (tid == 0) { STG(t, t, (13 + 2*t) % 14, (14 + 2*t) % 14); }
        V4 Oi1 = LSLOT(7 + 2*t);       // offset 2t+7
        V4 En2 = LSLOT(8 + 2*t);       // offset 2t+8
        CORE(En2, Oi1);
        if (lane == 0) mbar_arrive(EMPTYB(t + 4));
    }

    // ---- main blocks of 7: t = 3+7k+u, k = 0..2 full; constants per u ----
    // read slots: Oi1 (13+2u)%14, En2 (2u)%14 ; stage slots (5+2u)%14,(6+2u)%14
    // stage/empty group (3+u)%7 ; full group u
    #define STEPU(u, t_, pf_, skipE_) do {                                      \
        if (tid == 0) {                                                         \
            if (!(skipE_)) mbar_wait(EMPTYB((3 + (u)) % 7),                     \
                                     (u) == 0 ? ((pf_) ^ 1u) : (pf_));          \
            STG(t_, (3 + (u)) % 7, (5 + 2*(u)) % 14, (6 + 2*(u)) % 14);         \
        }                                                                       \
        mbar_wait(FULLB(u), pf_);                                               \
        V4 Oi1 = LSLOT((13 + 2*(u)) % 14);                                      \
        V4 En2 = LSLOT((2*(u)) % 14);                                           \
        CORE(En2, Oi1);                                                         \
        if (lane == 0) mbar_arrive(EMPTYB(u));                                  \
    } while (0)

    #pragma unroll 1
    for (int k = 0; k < 3; ++k) {
        const uint32_t pf = (uint32_t)(k & 1);
        const int tb = 3 + 7 * k;
        { STEPU(0, tb + 0, pf, (k == 0)); }
        { STEPU(1, tb + 1, pf, false); }
        { STEPU(2, tb + 2, pf, false); }
        { STEPU(3, tb + 3, pf, false); }
        { STEPU(4, tb + 4, pf, false); }
        { STEPU(5, tb + 5, pf, false); }
        { STEPU(6, tb + 6, pf, false); }
    }
    // ---- k = 3 partial: t = 24..28 (u = 0..4, pf = 1) ----
    { STEPU(0, 24, 1u, false); }
    { STEPU(1, 25, 1u, false); }
    { STEPU(2, 26, 1u, false); }
    { STEPU(3, 27, 1u, false); }
    { STEPU(4, 28, 1u, false); }

    // ---- tail: t = 29,30,31 — wait-only, reflection-capable (bottom CTA) ----
    {
        mbar_wait(FULLB(5), 1u);
        const int i = i0 + 29;
        V4 Oi1 = LGEN(2 * reflC(i + 1) + 1);
        V4 En2 = LGEN(2 * reflC(i + 2));
        CORE(En2, Oi1);
    }
    {
        mbar_wait(FULLB(6), 1u);
        const int i = i0 + 30;
        V4 Oi1 = LGEN(2 * reflC(i + 1) + 1);
        V4 En2 = LGEN(2 * reflC(i + 2));
        CORE(En2, Oi1);
    }
    {
        mbar_wait(FULLB(0), 0u);
        const int i = i0 + 31;
        V4 Oi1 = LGEN(2 * reflC(i + 1) + 1);
        V4 En2 = LGEN(2 * reflC(i + 2));
        CORE(En2, Oi1);
    }
    #undef STEPU
    #undef STG
    #undef CORE
    #undef LGEN
    #undef LSLOT
    #undef FULLB
    #undef PROB
    #undef EMPTYB
}

extern "C" void kernel_launch(void* const* d_in, const int* in_sizes, int n_in,
                              void* d_out, int out_size) {
    const float* x = (const float*)d_in[0];
    float* out = (float*)d_out;
    const int smem = RS * NN * sizeof(float);   // 57344
    cudaFuncSetAttribute(ilwt2d_occ4_kernel,
                         cudaFuncAttributeMaxDynamicSharedMemorySize, smem);
    dim3 grid(HH / TI, 24);   // 16 x 24 = 384 CTAs
    ilwt2d_occ4_kernel<<<grid, NTHREADS, smem>>>(x, out);
}

// round 16
// speedup vs baseline: 1.0271x; 1.0271x over previous
#include <cuda_runtime.h>
#include <cstdint>

#define NN 1024
#define HH 512
#define TI 16            // output rows per CTA
#define NWARPS 8
#define NTHREADS (NWARPS*32)
#define RS 14            // ring slots (raw rows); 14*4KB = 56KB -> 4 CTAs/SM
#define ROWB (NN*4)      // bytes per raw row

__device__ __forceinline__ int reflC(int c) {
    if (c < 0) c = -c;
    if (c > HH - 1) c = 2 * (HH - 1) - c;
    return c;
}

__device__ __forceinline__ void tma_row(uint32_t dst, const float* src, uint32_t mbar) {
    asm volatile(
        "cp.async.bulk.shared::cta.global.mbarrier::complete_tx::bytes [%0], [%1], %2, [%3];"
        :: "r"(dst), "l"(src), "r"((uint32_t)ROWB), "r"(mbar) : "memory");
}
__device__ __forceinline__ void mbar_init(uint32_t mbar, uint32_t cnt) {
    asm volatile("mbarrier.init.shared.b64 [%0], %1;" :: "r"(mbar), "r"(cnt) : "memory");
}
__device__ __forceinline__ void mbar_expect(uint32_t mbar, uint32_t bytes) {
    asm volatile("mbarrier.arrive.expect_tx.shared.b64 _, [%0], %1;"
                 :: "r"(mbar), "r"(bytes) : "memory");
}
__device__ __forceinline__ void mbar_arrive(uint32_t mbar) {
    asm volatile("mbarrier.arrive.shared.b64 _, [%0];" :: "r"(mbar) : "memory");
}
__device__ __forceinline__ void mbar_wait(uint32_t mbar, uint32_t parity) {
    asm volatile(
        "{\n\t.reg .pred P;\n\t"
        "W_%=:\n\t"
        "mbarrier.try_wait.parity.acquire.cta.shared::cta.b64 P, [%0], %1, 0x989680;\n\t"
        "@!P bra W_%=;\n\t"
        "}" :: "r"(mbar), "r"(parity) : "memory");
}
__device__ __forceinline__ void stcs2(float* p, float a, float b) {
    asm volatile("st.global.cs.v2.f32 [%0], {%1,%2};" :: "l"(p), "f"(a), "f"(b) : "memory");
}

struct V4 { float s0, s1, d0, d1; };

__device__ __forceinline__ V4 rowlift(const float* rp,
                                      int loff, int offA, int offC,
                                      bool lEdge, bool rEdge) {
    const float4 B = *reinterpret_cast<const float4*>(rp + loff);
    const float4 A = *reinterpret_cast<const float4*>(rp + offA);
    const float4 C = *reinterpret_cast<const float4*>(rp + offC);
    float dm1 = A.w - 0.5f * (A.x + B.x);
    float d0  = B.y - 0.5f * (A.z + B.z);
    float d1  = B.w - 0.5f * (B.x + C.x);
    float d2  = C.y - 0.5f * (B.z + C.z);
    if (lEdge) { dm1 = d1; d0 = B.y - B.z; }
    if (rEdge) { d1 = B.w - B.x; d2 = d0; }
    V4 r;
    r.s0 = B.x + 0.25f * (dm1 + d1);
    r.s1 = B.z + 0.25f * (d0 + d2);
    r.d0 = d0; r.d1 = d1;
    return r;
}

__global__ __launch_bounds__(NTHREADS, 4)
void ilwt2d_grid2_kernel(const float* __restrict__ x, float* __restrict__ out) {
    extern __shared__ __align__(16) float ring[];   // RS * NN floats = 56KB
    __shared__ __align__(8) uint64_t mbars[15];     // [0..6] full, [7] prologue, [8..14] empty

    const int tid  = threadIdx.x;
    const int lane = tid & 31;
    const int w    = tid >> 5;
    const int C0   = w * 64;
    const int i0   = blockIdx.x * TI;
    const int img  = blockIdx.y;
    const float* __restrict__ xp = x + (size_t)img * NN * NN;
    const int rbase = 2 * i0 - 4;

    const uint32_t sring = (uint32_t)__cvta_generic_to_shared(ring);
    const uint32_t mb0   = (uint32_t)__cvta_generic_to_shared(&mbars[0]);
    #define FULLB(g)  (mb0 + (uint32_t)((g) * 8))
    #define PROB()    (mb0 + 56u)
    #define EMPTYB(g) (mb0 + 64u + (uint32_t)((g) * 8))

    if (tid == 0) {
        #pragma unroll
        for (int j = 0; j < 7; ++j) mbar_init(FULLB(j), 1);
        mbar_init(PROB(), 1);
        #pragma unroll
        for (int j = 0; j < 7; ++j) mbar_init(EMPTYB(j), NWARPS);
    }
    __syncthreads();

    // ---- prologue staging: offsets 0..12 (13 rows), slots 0..12 ----
    if (tid == 0) {
        mbar_expect(PROB(), 13u * (uint32_t)ROWB);
        #pragma unroll
        for (int k = 0; k < 13; ++k) {
            int row = max(0, min(NN - 1, rbase + k));
            tma_row(sring + (uint32_t)(k * ROWB), xp + (size_t)row * NN, PROB());
        }
    }

    const int loff = 2 * C0 + 4 * lane;
    const bool lEdge = (loff == 0);
    const bool rEdge = (loff == NN - 4);
    const int offA = lEdge ? loff : loff - 4;
    const int offC = rEdge ? loff : loff + 4;

    #define LSLOT(s) rowlift(ring + (s) * NN, loff, offA, offC, lEdge, rEdge)
    #define LGEN(row_) rowlift(ring + (((row_) - rbase) % RS) * NN, \
                               loff, offA, offC, lEdge, rEdge)

    mbar_wait(PROB(), 0);           // prologue rows 0..12 visible

    // ---- prologue pipeline state (reads offsets 0..8 -> slot == offset) ----
    V4 Ecur  = LSLOT(4);                           // row 2*i0
    const int sm  = 2 * reflC(i0 - 1) - rbase;     // 2 (interior) / 6 (top)
    const int sm2 = 2 * reflC(i0 - 2) - rbase;     // 0 / 8
    V4 Em    = LSLOT(sm);
    V4 Em2   = LSLOT(sm2);
    V4 Om1   = LSLOT(sm + 1);
    V4 Dprev;
    Dprev.s0 = Om1.s0 - 0.5f * (Em2.s0 + Ecur.s0);
    Dprev.s1 = Om1.s1 - 0.5f * (Em2.s1 + Ecur.s1);
    Dprev.d0 = Om1.d0 - 0.5f * (Em2.d0 + Ecur.d0);
    Dprev.d1 = Om1.d1 - 0.5f * (Em2.d1 + Ecur.d1);
    V4 Enext = LSLOT(6);                           // row 2*(i0+1), always interior
    V4 O0    = LSLOT(5);                           // row 2*i0+1
    V4 Dcur;
    Dcur.s0 = O0.s0 - 0.5f * (Em.s0 + Enext.s0);
    Dcur.s1 = O0.s1 - 0.5f * (Em.s1 + Enext.s1);
    Dcur.d0 = O0.d0 - 0.5f * (Em.d0 + Enext.d0);
    Dcur.d1 = O0.d1 - 0.5f * (Em.d1 + Enext.d1);
    __syncthreads();   // all prologue ring reads complete before any main staging

    const int b = img / 3, ch = img - 3 * b;
    const size_t plane = (size_t)HH * HH;
    float* op = out + (size_t)b * 12 * plane + (size_t)ch * plane
                    + (size_t)i0 * HH + C0 + 2 * lane;

    #define CORE(En2, Oi1)                                                      \
        V4 Dnext;                                                               \
        Dnext.s0 = Oi1.s0 - 0.5f * (Ecur.s0 + En2.s0);                          \
        Dnext.s1 = Oi1.s1 - 0.5f * (Ecur.s1 + En2.s1);                          \
        Dnext.d0 = Oi1.d0 - 0.5f * (Ecur.d0 + En2.d0);                          \
        Dnext.d1 = Oi1.d1 - 0.5f * (Ecur.d1 + En2.d1);                          \
        float2 ll = { Ecur.s0 + 0.25f * (Dprev.s0 + Dnext.s0),                  \
                      Ecur.s1 + 0.25f * (Dprev.s1 + Dnext.s1) };                \
        float2 hl = { Ecur.d0 + 0.25f * (Dprev.d0 + Dnext.d0),                  \
                      Ecur.d1 + 0.25f * (Dprev.d1 + Dnext.d1) };                \
        stcs2(op,             ll.x, ll.y);                                      \
        stcs2(op + 3 * plane, Dcur.s0, Dcur.s1);                                \
        stcs2(op + 6 * plane, hl.x, hl.y);                                      \
        stcs2(op + 9 * plane, Dcur.d0, Dcur.d1);                                \
        op += HH;                                                               \
        Ecur = Enext; Enext = En2;                                              \
        Dprev = Dcur; Dcur = Dnext;

    // stage pair (2t+13, 2t+14) into group g at constant slots
    #define STG(t_, g_, s1_, s2_) do {                                          \
        mbar_expect(FULLB(g_), 2u * (uint32_t)ROWB);                            \
        int r1 = min(NN - 1, rbase + 2 * (t_) + 13);                            \
        int r2 = min(NN - 1, rbase + 2 * (t_) + 14);                            \
        tma_row(sring + (uint32_t)((s1_) * ROWB), xp + (size_t)r1 * NN, FULLB(g_)); \
        tma_row(sring + (uint32_t)((s2_) * ROWB), xp + (size_t)r2 * NN, FULLB(g_)); \
    } while (0)

    // ---- phase 1: t = 0..2 — consume prologue slots (no full wait), stage groups 0..2 ----
    #pragma unroll
    for (int t = 0; t < 3; ++t) {
        if (tid == 0) { STG(t, t, (13 + 2*t) % 14, (14 + 2*t) % 14); }
        V4 Oi1 = LSLOT(7 + 2*t);       // offset 2t+7
        V4 En2 = LSLOT(8 + 2*t);       // offset 2t+8
        CORE(En2, Oi1);
        if (lane == 0) mbar_arrive(EMPTYB(t + 4));
    }

    // read slots: Oi1 (13+2u)%14, En2 (2u)%14 ; stage slots (5+2u)%14,(6+2u)%14
    // stage/empty group (3+u)%7 ; full group u
    #define STEPU(u, t_, pf_, skipE_) do {                                      \
        if (tid == 0) {                                                         \
            if (!(skipE_)) mbar_wait(EMPTYB((3 + (u)) % 7),                     \
                                     (u) == 0 ? ((pf_) ^ 1u) : (pf_));          \
            STG(t_, (3 + (u)) % 7, (5 + 2*(u)) % 14, (6 + 2*(u)) % 14);         \
        }                                                                       \
        mbar_wait(FULLB(u), pf_);                                               \
        V4 Oi1 = LSLOT((13 + 2*(u)) % 14);                                      \
        V4 En2 = LSLOT((2*(u)) % 14);                                           \
        CORE(En2, Oi1);                                                         \
        if (lane == 0) mbar_arrive(EMPTYB(u));                                  \
    } while (0)

    // ---- main: one full 7-block (t = 3..9, pf = 0) ----
    { STEPU(0, 3, 0u, true); }      // group 3 slots freed by prologue syncthreads
    { STEPU(1, 4, 0u, false); }
    { STEPU(2, 5, 0u, false); }
    { STEPU(3, 6, 0u, false); }
    { STEPU(4, 7, 0u, false); }
    { STEPU(5, 8, 0u, false); }
    { STEPU(6, 9, 0u, false); }
    // ---- partial block: t = 10..12 (u = 0..2, pf = 1) ----
    { STEPU(0, 10, 1u, false); }
    { STEPU(1, 11, 1u, false); }
    { STEPU(2, 12, 1u, false); }

    // ---- tail: t = 13,14,15 — wait-only, reflection-capable (bottom CTA) ----
    {
        mbar_wait(FULLB(3), 1u);
        const int i = i0 + 13;
        V4 Oi1 = LGEN(2 * reflC(i + 1) + 1);
        V4 En2 = LGEN(2 * reflC(i + 2));
        CORE(En2, Oi1);
    }
    {
        mbar_wait(FULLB(4), 1u);
        const int i = i0 + 14;
        V4 Oi1 = LGEN(2 * reflC(i + 1) + 1);
        V4 En2 = LGEN(2 * reflC(i + 2));
        CORE(En2, Oi1);
    }
    {
        mbar_wait(FULLB(5), 1u);
        const int i = i0 + 15;
        V4 Oi1 = LGEN(2 * reflC(i + 1) + 1);
        V4 En2 = LGEN(2 * reflC(i + 2));
        CORE(En2, Oi1);
    }
    #undef STEPU
    #undef STG
    #undef CORE
    #undef LGEN
    #undef LSLOT
    #undef FULLB
    #undef PROB
    #undef EMPTYB
}

extern "C" void kernel_launch(void* const* d_in, const int* in_sizes, int n_in,
                              void* d_out, int out_size) {
    const float* x = (const float*)d_in[0];
    float* out = (float*)d_out;
    const int smem = RS * NN * sizeof(float);   // 57344
    cudaFuncSetAttribute(ilwt2d_grid2_kernel,
                         cudaFuncAttributeMaxDynamicSharedMemorySize, smem);
    dim3 grid(HH / TI, 24);   // 32 x 24 = 768 CTAs
    ilwt2d_grid2_kernel<<<grid, NTHREADS, smem>>>(x, out);
}

// round 17
// speedup vs baseline: 1.0297x; 1.0025x over previous
#include <cuda_runtime.h>
#include <cstdint>

#define NN 1024
#define HH 512
#define TI 16            // output rows per CTA
#define NWARPS 8
#define NTHREADS (NWARPS*32)
#define RS 14            // ring slots (raw rows); 14*4KB = 56KB
#define ROWB (NN*4)      // bytes per raw row

__device__ __forceinline__ int reflC(int c) {
    if (c < 0) c = -c;
    if (c > HH - 1) c = 2 * (HH - 1) - c;
    return c;
}

// L2 evict-last policy: pin the input tensor (100.7MB < 126MB L2) across replays
__device__ __forceinline__ uint64_t mkpol_evict_last() {
    uint64_t p;
    asm("createpolicy.fractional.L2::evict_last.b64 %0, 1.0;" : "=l"(p));
    return p;
}

__device__ __forceinline__ void tma_row(uint32_t dst, const float* src, uint32_t mbar,
                                        uint64_t pol) {
    asm volatile(
        "cp.async.bulk.shared::cta.global.mbarrier::complete_tx::bytes.L2::cache_hint "
        "[%0], [%1], %2, [%3], %4;"
        :: "r"(dst), "l"(src), "r"((uint32_t)ROWB), "r"(mbar), "l"(pol) : "memory");
}
__device__ __forceinline__ void mbar_init(uint32_t mbar, uint32_t cnt) {
    asm volatile("mbarrier.init.shared.b64 [%0], %1;" :: "r"(mbar), "r"(cnt) : "memory");
}
__device__ __forceinline__ void mbar_expect(uint32_t mbar, uint32_t bytes) {
    asm volatile("mbarrier.arrive.expect_tx.shared.b64 _, [%0], %1;"
                 :: "r"(mbar), "r"(bytes) : "memory");
}
__device__ __forceinline__ void mbar_arrive(uint32_t mbar) {
    asm volatile("mbarrier.arrive.shared.b64 _, [%0];" :: "r"(mbar) : "memory");
}
__device__ __forceinline__ void mbar_wait(uint32_t mbar, uint32_t parity) {
    asm volatile(
        "{\n\t.reg .pred P;\n\t"
        "W_%=:\n\t"
        "mbarrier.try_wait.parity.acquire.cta.shared::cta.b64 P, [%0], %1, 0x989680;\n\t"
        "@!P bra W_%=;\n\t"
        "}" :: "r"(mbar), "r"(parity) : "memory");
}
__device__ __forceinline__ void stcs2(float* p, float a, float b) {
    asm volatile("st.global.cs.v2.f32 [%0], {%1,%2};" :: "l"(p), "f"(a), "f"(b) : "memory");
}

struct V4 { float s0, s1, d0, d1; };

__device__ __forceinline__ V4 rowlift(const float* rp,
                                      int loff, int offA, int offC,
                                      bool lEdge, bool rEdge) {
    const float4 B = *reinterpret_cast<const float4*>(rp + loff);
    const float4 A = *reinterpret_cast<const float4*>(rp + offA);
    const float4 C = *reinterpret_cast<const float4*>(rp + offC);
    float dm1 = A.w - 0.5f * (A.x + B.x);
    float d0  = B.y - 0.5f * (A.z + B.z);
    float d1  = B.w - 0.5f * (B.x + C.x);
    float d2  = C.y - 0.5f * (B.z + C.z);
    if (lEdge) { dm1 = d1; d0 = B.y - B.z; }
    if (rEdge) { d1 = B.w - B.x; d2 = d0; }
    V4 r;
    r.s0 = B.x + 0.25f * (dm1 + d1);
    r.s1 = B.z + 0.25f * (d0 + d2);
    r.d0 = d0; r.d1 = d1;
    return r;
}

__global__ __launch_bounds__(NTHREADS, 4)
void ilwt2d_pin_kernel(const float* __restrict__ x, float* __restrict__ out) {
    extern __shared__ __align__(16) float ring[];   // RS * NN floats = 56KB
    __shared__ __align__(8) uint64_t mbars[15];     // [0..6] full, [7] prologue, [8..14] empty

    const int tid  = threadIdx.x;
    const int lane = tid & 31;
    const int w    = tid >> 5;
    const int C0   = w * 64;
    const int i0   = blockIdx.x * TI;
    const int img  = blockIdx.y;
    const float* __restrict__ xp = x + (size_t)img * NN * NN;
    const int rbase = 2 * i0 - 4;

    const uint32_t sring = (uint32_t)__cvta_generic_to_shared(ring);
    const uint32_t mb0   = (uint32_t)__cvta_generic_to_shared(&mbars[0]);
    const uint64_t pol   = mkpol_evict_last();
    #define FULLB(g)  (mb0 + (uint32_t)((g) * 8))
    #define PROB()    (mb0 + 56u)
    #define EMPTYB(g) (mb0 + 64u + (uint32_t)((g) * 8))

    if (tid == 0) {
        #pragma unroll
        for (int j = 0; j < 7; ++j) mbar_init(FULLB(j), 1);
        mbar_init(PROB(), 1);
        #pragma unroll
        for (int j = 0; j < 7; ++j) mbar_init(EMPTYB(j), NWARPS);
    }
    __syncthreads();

    // ---- prologue staging: offsets 0..12 (13 rows), slots 0..12 ----
    if (tid == 0) {
        mbar_expect(PROB(), 13u * (uint32_t)ROWB);
        #pragma unroll
        for (int k = 0; k < 13; ++k) {
            int row = max(0, min(NN - 1, rbase + k));
            tma_row(sring + (uint32_t)(k * ROWB), xp + (size_t)row * NN, PROB(), pol);
        }
    }

    const int loff = 2 * C0 + 4 * lane;
    const bool lEdge = (loff == 0);
    const bool rEdge = (loff == NN - 4);
    const int offA = lEdge ? loff : loff - 4;
    const int offC = rEdge ? loff : loff + 4;

    #define LSLOT(s) rowlift(ring + (s) * NN, loff, offA, offC, lEdge, rEdge)
    #define LGEN(row_) rowlift(ring + (((row_) - rbase) % RS) * NN, \
                               loff, offA, offC, lEdge, rEdge)

    mbar_wait(PROB(), 0);           // prologue rows 0..12 visible

    // ---- prologue pipeline state (reads offsets 0..8 -> slot == offset) ----
    V4 Ecur  = LSLOT(4);                           // row 2*i0
    const int sm  = 2 * reflC(i0 - 1) - rbase;     // 2 (interior) / 6 (top)
    const int sm2 = 2 * reflC(i0 - 2) - rbase;     // 0 / 8
    V4 Em    = LSLOT(sm);
    V4 Em2   = LSLOT(sm2);
    V4 Om1   = LSLOT(sm + 1);
    V4 Dprev;
    Dprev.s0 = Om1.s0 - 0.5f * (Em2.s0 + Ecur.s0);
    Dprev.s1 = Om1.s1 - 0.5f * (Em2.s1 + Ecur.s1);
    Dprev.d0 = Om1.d0 - 0.5f * (Em2.d0 + Ecur.d0);
    Dprev.d1 = Om1.d1 - 0.5f * (Em2.d1 + Ecur.d1);
    V4 Enext = LSLOT(6);                           // row 2*(i0+1), always interior
    V4 O0    = LSLOT(5);                           // row 2*i0+1
    V4 Dcur;
    Dcur.s0 = O0.s0 - 0.5f * (Em.s0 + Enext.s0);
    Dcur.s1 = O0.s1 - 0.5f * (Em.s1 + Enext.s1);
    Dcur.d0 = O0.d0 - 0.5f * (Em.d0 + Enext.d0);
    Dcur.d1 = O0.d1 - 0.5f * (Em.d1 + Enext.d1);
    __syncthreads();   // all prologue ring reads complete before any main staging

    const int b = img / 3, ch = img - 3 * b;
    const size_t plane = (size_t)HH * HH;
    float* op = out + (size_t)b * 12 * plane + (size_t)ch * plane
                    + (size_t)i0 * HH + C0 + 2 * lane;

    #define CORE(En2, Oi1)                                                      \
        V4 Dnext;                                                               \
        Dnext.s0 = Oi1.s0 - 0.5f * (Ecur.s0 + En2.s0);                          \
        Dnext.s1 = Oi1.s1 - 0.5f * (Ecur.s1 + En2.s1);                          \
        Dnext.d0 = Oi1.d0 - 0.5f * (Ecur.d0 + En2.d0);                          \
        Dnext.d1 = Oi1.d1 - 0.5f * (Ecur.d1 + En2.d1);                          \
        float2 ll = { Ecur.s0 + 0.25f * (Dprev.s0 + Dnext.s0),                  \
                      Ecur.s1 + 0.25f * (Dprev.s1 + Dnext.s1) };                \
        float2 hl = { Ecur.d0 + 0.25f * (Dprev.d0 + Dnext.d0),                  \
                      Ecur.d1 + 0.25f * (Dprev.d1 + Dnext.d1) };                \
        stcs2(op,             ll.x, ll.y);                                      \
        stcs2(op + 3 * plane, Dcur.s0, Dcur.s1);                                \
        stcs2(op + 6 * plane, hl.x, hl.y);                                      \
        stcs2(op + 9 * plane, Dcur.d0, Dcur.d1);                                \
        op += HH;                                                               \
        Ecur = Enext; Enext = En2;                                              \
        Dprev = Dcur; Dcur = Dnext;

    // stage pair (2t+13, 2t+14) into group g at constant slots
    #define STG(t_, g_, s1_, s2_) do {                                          \
        mbar_expect(FULLB(g_), 2u * (uint32_t)ROWB);                            \
        int r1 = min(NN - 1, rbase + 2 * (t_) + 13);                            \
        int r2 = min(NN - 1, rbase + 2 * (t_) + 14);                            \
        tma_row(sring + (uint32_t)((s1_) * ROWB), xp + (size_t)r1 * NN, FULLB(g_), pol); \
        tma_row(sring + (uint32_t)((s2_) * ROWB), xp + (size_t)r2 * NN, FULLB(g_), pol); \
    } while (0)

    // ---- phase 1: t = 0..2 — consume prologue slots (no full wait), stage groups 0..2 ----
    #pragma unroll
    for (int t = 0; t < 3; ++t) {
        if (tid == 0) { STG(t, t, (13 + 2*t) % 14, (14 + 2*t) % 14); }
        V4 Oi1 = LSLOT(7 + 2*t);       // offset 2t+7
        V4 En2 = LSLOT(8 + 2*t);       // offset 2t+8
        CORE(En2, Oi1);
        if (lane == 0) mbar_arrive(EMPTYB(t + 4));
    }

    // read slots: Oi1 (13+2u)%14, En2 (2u)%14 ; stage slots (5+2u)%14,(6+2u)%14
    // stage/empty group (3+u)%7 ; full group u
    #define STEPU(u, t_, pf_, skipE_) do {                                      \
        if (tid == 0) {                                                         \
            if (!(skipE_)) mbar_wait(EMPTYB((3 + (u)) % 7),                     \
                                     (u) == 0 ? ((pf_) ^ 1u) : (pf_));          \
            STG(t_, (3 + (u)) % 7, (5 + 2*(u)) % 14, (6 + 2*(u)) % 14);         \
        }                                                                       \
        mbar_wait(FULLB(u), pf_);                                               \
        V4 Oi1 = LSLOT((13 + 2*(u)) % 14);                                      \
        V4 En2 = LSLOT((2*(u)) % 14);                                           \
        CORE(En2, Oi1);                                                         \
        if (lane == 0) mbar_arrive(EMPTYB(u));                                  \
    } while (0)

    // ---- main: one full 7-block (t = 3..9, pf = 0) ----
    { STEPU(0, 3, 0u, true); }      // group 3 slots freed by prologue syncthreads
    { STEPU(1, 4, 0u, false); }
    { STEPU(2, 5, 0u, false); }
    { STEPU(3, 6, 0u, false); }
    { STEPU(4, 7, 0u, false); }
    { STEPU(5, 8, 0u, false); }
    { STEPU(6, 9, 0u, false); }
    // ---- partial block: t = 10..12 (u = 0..2, pf = 1) ----
    { STEPU(0, 10, 1u, false); }
    { STEPU(1, 11, 1u, false); }
    { STEPU(2, 12, 1u, false); }

    // ---- tail: t = 13,14,15 — wait-only, reflection-capable (bottom CTA) ----
    {
        mbar_wait(FULLB(3), 1u);
        const int i = i0 + 13;
        V4 Oi1 = LGEN(2 * reflC(i + 1) + 1);
        V4 En2 = LGEN(2 * reflC(i + 2));
        CORE(En2, Oi1);
    }
    {
        mbar_wait(FULLB(4), 1u);
        const int i = i0 + 14;
        V4 Oi1 = LGEN(2 * reflC(i + 1) + 1);
        V4 En2 = LGEN(2 * reflC(i + 2));
        CORE(En2, Oi1);
    }
    {
        mbar_wait(FULLB(5), 1u);
        const int i = i0 + 15;
        V4 Oi1 = LGEN(2 * reflC(i + 1) + 1);
        V4 En2 = LGEN(2 * reflC(i + 2));
        CORE(En2, Oi1);
    }
    #undef STEPU
    #undef STG
    #undef CORE
    #undef LGEN
    #undef LSLOT
    #undef FULLB
    #undef PROB
    #undef EMPTYB
}

extern "C" void kernel_launch(void* const* d_in, const int* in_sizes, int n_in,
                              void* d_out, int out_size) {
    const float* x = (const float*)d_in[0];
    float* out = (float*)d_out;
    const int smem = RS * NN * sizeof(float);   // 57344
    cudaFuncSetAttribute(ilwt2d_pin_kernel,
                         cudaFuncAttributeMaxDynamicSharedMemorySize, smem);
    dim3 grid(HH / TI, 24);   // 32 x 24 = 768 CTAs
    ilwt2d_pin_kernel<<<grid, NTHREADS, smem>>>(x, out);
}